// round 1
// baseline (speedup 1.0000x reference)
#include <cuda_runtime.h>
#include <cuda_bf16.h>
#include <cstdint>
#include <cstddef>

#define BATCH 4
#define CDIM  512
#define KDIM  64
#define NDIM  4096
#define NN    ((size_t)NDIM * NDIM)

// ---------------- device scratch (no allocs allowed) ----------------
__device__ __align__(16) __nv_bfloat16 d_fa_hi[BATCH * NDIM * KDIM]; // f, i-major [b][i][k]
__device__ __align__(16) __nv_bfloat16 d_fa_lo[BATCH * NDIM * KDIM];
__device__ __align__(16) __nv_bfloat16 d_gb_hi[BATCH * NDIM * KDIM]; // g, j-major [b][j][k]
__device__ __align__(16) __nv_bfloat16 d_gb_lo[BATCH * NDIM * KDIM];
__device__ float d_Z[BATCH * NDIM];       // column sums of exp(s)
__device__ float d_rowsum[BATCH * NDIM];  // row sums of beta
__device__ float d_y[BATCH * CDIM];
__device__ float d_xbar[BATCH * CDIM];

__device__ __forceinline__ float fast_exp(float x) {
    float y;
    asm("ex2.approx.ftz.f32 %0, %1;" : "=f"(y) : "f"(x * 1.4426950408889634f));
    return y;
}

__device__ __forceinline__ float warp_sum(float v) {
    #pragma unroll
    for (int o = 16; o; o >>= 1) v += __shfl_xor_sync(0xFFFFFFFFu, v, o);
    return v;
}

// ---------------- zero scratch accumulators ----------------
__global__ void zero_kernel() {
    int i = blockIdx.x * blockDim.x + threadIdx.x;
    if (i < BATCH * NDIM) { d_Z[i] = 0.f; d_rowsum[i] = 0.f; }
}

// ---------------- FG: [f;g] = [Wq;Wk] @ x[b], split to bf16 hi/lo ----------------
// grid (32, BATCH), 256 threads.  Tile: [128 m] x [128 i], K=512.
#define WS_STRIDE 136
#define FG_SMEM (128 * 129 * 4)  // 66048 bytes (>= operand region 33792)

__global__ __launch_bounds__(256) void fg_kernel(const float* __restrict__ x,
                                                 const float* __restrict__ Wq,
                                                 const float* __restrict__ Wk) {
    extern __shared__ char dynsm[];
    float* Ws = (float*)dynsm;                 // [32][136]
    float* Xs = Ws + 32 * WS_STRIDE;           // [32][128]
    float* S  = (float*)dynsm;                 // [128][129] (aliases after loop)

    int b = blockIdx.y;
    int i0 = blockIdx.x * 128;
    int tid = threadIdx.x;
    int tx = tid & 15, ty = tid >> 4;
    const float* xb = x + (size_t)b * CDIM * NDIM;

    float acc[8][8];
    #pragma unroll
    for (int r = 0; r < 8; r++)
        #pragma unroll
        for (int s = 0; s < 8; s++) acc[r][s] = 0.f;

    for (int c0 = 0; c0 < CDIM; c0 += 32) {
        // W chunk [128 m][32 c] -> Ws[c][m]
        for (int idx = tid; idx < 128 * 32; idx += 256) {
            int m = idx >> 5, c = idx & 31;
            float w = (m < 64) ? Wq[m * CDIM + c0 + c] : Wk[(m - 64) * CDIM + c0 + c];
            Ws[c * WS_STRIDE + m] = w;
        }
        // x chunk [32 c][128 i]
        for (int idx = tid; idx < 32 * 32; idx += 256) {
            int c = idx >> 5, q = idx & 31;
            ((float4*)Xs)[c * 32 + q] =
                ((const float4*)(xb + (size_t)(c0 + c) * NDIM + i0))[q];
        }
        __syncthreads();
        #pragma unroll 4
        for (int kc = 0; kc < 32; kc++) {
            float am[8];
            #pragma unroll
            for (int r = 0; r < 8; r++) am[r] = Ws[kc * WS_STRIDE + ty * 8 + r];
            float4 xv0 = *(const float4*)(Xs + kc * 128 + tx * 8);
            float4 xv1 = *(const float4*)(Xs + kc * 128 + tx * 8 + 4);
            float xi[8] = {xv0.x, xv0.y, xv0.z, xv0.w, xv1.x, xv1.y, xv1.z, xv1.w};
            #pragma unroll
            for (int r = 0; r < 8; r++)
                #pragma unroll
                for (int s = 0; s < 8; s++) acc[r][s] += am[r] * xi[s];
        }
        __syncthreads();
    }

    // stage fp32 tile S[m][i]
    #pragma unroll
    for (int r = 0; r < 8; r++)
        #pragma unroll
        for (int s = 0; s < 8; s++)
            S[(ty * 8 + r) * 129 + tx * 8 + s] = acc[r][s];
    __syncthreads();

    // write split bf16: warp per row; lane -> (array, chunk)
    int wid = tid >> 5, lane = tid & 31;
    int arr = lane >> 3, chunk = lane & 7;
    int mbase = (arr >= 2 ? 64 : 0) + chunk * 8;
    __nv_bfloat16* dst = (arr == 0) ? d_fa_hi : (arr == 1) ? d_fa_lo
                       : (arr == 2) ? d_gb_hi : d_gb_lo;
    for (int r = wid; r < 128; r += 8) {
        __align__(16) __nv_bfloat16 vals[8];
        #pragma unroll
        for (int e = 0; e < 8; e++) {
            float v = S[(mbase + e) * 129 + r];
            __nv_bfloat16 hi = __float2bfloat16(v);
            if (arr & 1) vals[e] = __float2bfloat16(v - __bfloat162float(hi));
            else         vals[e] = hi;
        }
        *(uint4*)(dst + ((size_t)b * NDIM + i0 + r) * KDIM + chunk * 8) = *(uint4*)vals;
    }
}

// ---------------- attention passes: S = f^T g (split-bf16, 3 terms) ----------------
// grid (32,32,BATCH) = (jtile, itile, b), 256 threads (8 warps, 2x4 warp grid).
// PASS 1: Z[b,j] += sum_i exp(s).  PASS 2: beta = exp(s)/Z, rowsum += sum_j beta.
#define ATTN_SMEM 68096  // max(operands 65536, S 67584 + sZ 512)

template <int PASS>
__global__ __launch_bounds__(256, 2) void attn_kernel(float* __restrict__ beta_out) {
    extern __shared__ char dynsm[];
    __nv_bfloat16* sAhi = (__nv_bfloat16*)dynsm;   // [128][64] each, SW-swizzled
    __nv_bfloat16* sAlo = sAhi + 128 * 64;
    __nv_bfloat16* sBhi = sAlo + 128 * 64;
    __nv_bfloat16* sBlo = sBhi + 128 * 64;
    float* S  = (float*)dynsm;                      // [128][132] fp32 (alias)
    float* sZ = (float*)(dynsm + 67584);            // [128]

    int b  = blockIdx.z;
    int i0 = blockIdx.y * 128;
    int j0 = blockIdx.x * 128;
    int tid = threadIdx.x;
    int lane = tid & 31, wid = tid >> 5;
    int wm = wid >> 2, wn = wid & 3;

    if (PASS == 2 && tid < 128)
        sZ[tid] = 1.0f / d_Z[b * NDIM + j0 + tid];

    {   // load 4 operand tiles with XOR-16B swizzle
        const uint4* gAhi = (const uint4*)(d_fa_hi + ((size_t)b * NDIM + i0) * KDIM);
        const uint4* gAlo = (const uint4*)(d_fa_lo + ((size_t)b * NDIM + i0) * KDIM);
        const uint4* gBhi = (const uint4*)(d_gb_hi + ((size_t)b * NDIM + j0) * KDIM);
        const uint4* gBlo = (const uint4*)(d_gb_lo + ((size_t)b * NDIM + j0) * KDIM);
        for (int idx = tid; idx < 1024; idx += 256) {
            int r = idx >> 3, ch = idx & 7;
            int soff = r * 8 + (ch ^ (r & 7));
            ((uint4*)sAhi)[soff] = gAhi[idx];
            ((uint4*)sAlo)[soff] = gAlo[idx];
            ((uint4*)sBhi)[soff] = gBhi[idx];
            ((uint4*)sBlo)[soff] = gBlo[idx];
        }
    }
    __syncthreads();

    float acc[4][4][4];
    #pragma unroll
    for (int mf = 0; mf < 4; mf++)
        #pragma unroll
        for (int nf = 0; nf < 4; nf++)
            #pragma unroll
            for (int e = 0; e < 4; e++) acc[mf][nf][e] = 0.f;

    #pragma unroll
    for (int term = 0; term < 3; term++) {
        const __nv_bfloat16* At = (term == 2) ? sAlo : sAhi;
        const __nv_bfloat16* Bt = (term == 1) ? sBlo : sBhi;
        uint32_t aTile = (uint32_t)__cvta_generic_to_shared(At);
        uint32_t bTile = (uint32_t)__cvta_generic_to_shared(Bt);
        #pragma unroll
        for (int ks = 0; ks < 4; ks++) {
            int kc = ks * 2;  // 16B-chunk index of this k16 step
            uint32_t a[4][4], bb[4][2];
            #pragma unroll
            for (int mf = 0; mf < 4; mf++) {
                int r = wm * 64 + mf * 16 + (lane & 15);
                int c = kc + (lane >> 4);
                uint32_t addr = aTile + r * 128 + ((c ^ (r & 7)) << 4);
                asm volatile("ldmatrix.sync.aligned.m8n8.x4.shared.b16 {%0,%1,%2,%3}, [%4];"
                             : "=r"(a[mf][0]), "=r"(a[mf][1]), "=r"(a[mf][2]), "=r"(a[mf][3])
                             : "r"(addr));
            }
            #pragma unroll
            for (int nf = 0; nf < 4; nf++) {
                int r = wn * 32 + nf * 8 + (lane & 7);
                int c = kc + ((lane >> 3) & 1);
                uint32_t addr = bTile + r * 128 + ((c ^ (r & 7)) << 4);
                asm volatile("ldmatrix.sync.aligned.m8n8.x2.shared.b16 {%0,%1}, [%2];"
                             : "=r"(bb[nf][0]), "=r"(bb[nf][1]) : "r"(addr));
            }
            #pragma unroll
            for (int mf = 0; mf < 4; mf++)
                #pragma unroll
                for (int nf = 0; nf < 4; nf++)
                    asm volatile(
                        "mma.sync.aligned.m16n8k16.row.col.f32.bf16.bf16.f32 "
                        "{%0,%1,%2,%3}, {%4,%5,%6,%7}, {%8,%9}, {%0,%1,%2,%3};"
                        : "+f"(acc[mf][nf][0]), "+f"(acc[mf][nf][1]),
                          "+f"(acc[mf][nf][2]), "+f"(acc[mf][nf][3])
                        : "r"(a[mf][0]), "r"(a[mf][1]), "r"(a[mf][2]), "r"(a[mf][3]),
                          "r"(bb[nf][0]), "r"(bb[nf][1]));
        }
    }
    __syncthreads();  // operands dead; reuse smem for S

    #pragma unroll
    for (int mf = 0; mf < 4; mf++)
        #pragma unroll
        for (int nf = 0; nf < 4; nf++) {
            int r = wm * 64 + mf * 16 + (lane >> 2);
            int cc = wn * 32 + nf * 8 + (lane & 3) * 2;
            S[r * 132 + cc]           = acc[mf][nf][0];
            S[r * 132 + cc + 1]       = acc[mf][nf][1];
            S[(r + 8) * 132 + cc]     = acc[mf][nf][2];
            S[(r + 8) * 132 + cc + 1] = acc[mf][nf][3];
        }
    __syncthreads();

    if (PASS == 1) {
        int c = tid & 127, half = tid >> 7;
        float s = 0.f;
        #pragma unroll 8
        for (int r = half * 64; r < half * 64 + 64; r++) s += fast_exp(S[r * 132 + c]);
        atomicAdd(&d_Z[b * NDIM + j0 + c], s);
    } else {
        float* out = beta_out + (size_t)b * NN + (size_t)i0 * NDIM + j0;
        // 128 rows x 32 float4; each iteration: whole warp on one row
        for (int idx = tid; idx < 128 * 32; idx += 256) {
            int r = idx >> 5, q = idx & 31;
            float4 v;
            v.x = fast_exp(S[r * 132 + q * 4 + 0]) * sZ[q * 4 + 0];
            v.y = fast_exp(S[r * 132 + q * 4 + 1]) * sZ[q * 4 + 1];
            v.z = fast_exp(S[r * 132 + q * 4 + 2]) * sZ[q * 4 + 2];
            v.w = fast_exp(S[r * 132 + q * 4 + 3]) * sZ[q * 4 + 3];
            *(float4*)(out + (size_t)r * NDIM + q * 4) = v;
            float rsum = warp_sum(v.x + v.y + v.z + v.w);
            if (lane == 0) atomicAdd(&d_rowsum[b * NDIM + i0 + r], rsum);
        }
    }
}

// ---------------- pooled epilogue ----------------
// y[b,c'] = (1/N) sum_i x[b,c',i]*rowsum[b,i];  xbar[b,c] = mean_i x
__global__ __launch_bounds__(256) void pool1_kernel(const float* __restrict__ x) {
    int b = blockIdx.y;
    int cc = blockIdx.x * 8 + (threadIdx.x >> 5);
    int lane = threadIdx.x & 31;
    const float* xr = x + ((size_t)b * CDIM + cc) * NDIM;
    const float* rs = d_rowsum + b * NDIM;
    float ay = 0.f, ax = 0.f;
    for (int i = lane; i < NDIM; i += 32) {
        float xv = xr[i];
        ay += xv * rs[i];
        ax += xv;
    }
    ay = warp_sum(ay); ax = warp_sum(ax);
    if (lane == 0) {
        d_y[b * CDIM + cc]    = ay * (1.0f / NDIM);
        d_xbar[b * CDIM + cc] = ax * (1.0f / NDIM);
    }
}

// pooled[b,c] = gamma * sum_c' Wv[c,c'] y[b,c'] + xbar[b,c]
__global__ __launch_bounds__(256) void pool2_kernel(const float* __restrict__ Wv,
                                                    const float* __restrict__ gamma,
                                                    float* __restrict__ out) {
    int b = blockIdx.y;
    int c = blockIdx.x * 8 + (threadIdx.x >> 5);
    int lane = threadIdx.x & 31;
    const float* wr = Wv + (size_t)c * CDIM;
    const float* yb = d_y + b * CDIM;
    float a = 0.f;
    for (int k = lane; k < CDIM; k += 32) a += wr[k] * yb[k];
    a = warp_sum(a);
    if (lane == 0) out[b * CDIM + c] = gamma[0] * a + d_xbar[b * CDIM + c];
}

// ---------------- launch ----------------
extern "C" void kernel_launch(void* const* d_in, const int* in_sizes, int n_in,
                              void* d_out, int out_size) {
    const float* x     = (const float*)d_in[0];
    const float* Wq    = (const float*)d_in[1];
    const float* Wk    = (const float*)d_in[2];
    const float* Wv    = (const float*)d_in[3];
    const float* gamma = (const float*)d_in[4];
    float* out    = (float*)d_out;
    float* pooled = out;                    // [B,C,1,1] = 2048 floats
    float* beta   = out + BATCH * CDIM;     // [B,N,N]

    cudaFuncSetAttribute(fg_kernel, cudaFuncAttributeMaxDynamicSharedMemorySize, FG_SMEM);
    cudaFuncSetAttribute(attn_kernel<1>, cudaFuncAttributeMaxDynamicSharedMemorySize, ATTN_SMEM);
    cudaFuncSetAttribute(attn_kernel<2>, cudaFuncAttributeMaxDynamicSharedMemorySize, ATTN_SMEM);

    zero_kernel<<<64, 256>>>();
    fg_kernel<<<dim3(32, BATCH), 256, FG_SMEM>>>(x, Wq, Wk);
    attn_kernel<1><<<dim3(32, 32, BATCH), 256, ATTN_SMEM>>>(beta);
    attn_kernel<2><<<dim3(32, 32, BATCH), 256, ATTN_SMEM>>>(beta);
    pool1_kernel<<<dim3(CDIM / 8, BATCH), 256>>>(x);
    pool2_kernel<<<dim3(CDIM / 8, BATCH), 256>>>(Wv, gamma, pooled);
}

// round 3
// speedup vs baseline: 2.5111x; 2.5111x over previous
#include <cuda_runtime.h>
#include <cuda_bf16.h>
#include <cstdint>
#include <cstddef>

#define BATCH 4
#define CDIM  512
#define KDIM  64
#define NDIM  4096
#define NN    ((size_t)NDIM * NDIM)

// ---------------- device scratch (no allocs allowed) ----------------
__device__ __align__(16) __nv_bfloat16 d_fa_hi[BATCH * NDIM * KDIM]; // f, i-major [b][i][k]
__device__ __align__(16) __nv_bfloat16 d_fa_lo[BATCH * NDIM * KDIM];
__device__ __align__(16) __nv_bfloat16 d_gb_hi[BATCH * NDIM * KDIM]; // g, j-major [b][j][k]
__device__ __align__(16) __nv_bfloat16 d_gb_lo[BATCH * NDIM * KDIM];
__device__ __align__(16) __nv_bfloat16 d_w_hi[128 * CDIM];           // [Wq;Wk] split
__device__ __align__(16) __nv_bfloat16 d_w_lo[128 * CDIM];
__device__ float d_Z[BATCH * NDIM];       // column sums of exp(s)
__device__ float d_rowsum[BATCH * NDIM];  // row sums of beta
__device__ float d_y[BATCH * CDIM];
__device__ float d_xbar[BATCH * CDIM];

__device__ __forceinline__ float fast_exp(float x) {
    float y;
    asm("ex2.approx.ftz.f32 %0, %1;" : "=f"(y) : "f"(x * 1.4426950408889634f));
    return y;
}

__device__ __forceinline__ float warp_sum(float v) {
    #pragma unroll
    for (int o = 16; o; o >>= 1) v += __shfl_xor_sync(0xFFFFFFFFu, v, o);
    return v;
}

__device__ __forceinline__ uint32_t smem_u32(const void* p) {
    uint32_t a;
    asm("{ .reg .u64 t; cvta.to.shared.u64 t, %1; cvt.u32.u64 %0, t; }"
        : "=r"(a) : "l"(p));
    return a;
}

// A fragment (m16 x k16) via ldmatrix x4 from m-major SW-swizzled [128][64] bf16 tile
__device__ __forceinline__ void ldA(uint32_t tile, int rbase, int kc, int lane, uint32_t* a) {
    int r = rbase + (lane & 15);
    int c = kc + (lane >> 4);
    uint32_t addr = tile + r * 128 + ((c ^ (r & 7)) << 4);
    asm volatile("ldmatrix.sync.aligned.m8n8.x4.shared.b16 {%0,%1,%2,%3}, [%4];"
                 : "=r"(a[0]), "=r"(a[1]), "=r"(a[2]), "=r"(a[3]) : "r"(addr));
}

// B fragment (n8 x k16) via ldmatrix x2 from n-major SW-swizzled tile
__device__ __forceinline__ void ldB(uint32_t tile, int rbase, int kc, int lane, uint32_t* bb) {
    int r = rbase + (lane & 7);
    int c = kc + ((lane >> 3) & 1);
    uint32_t addr = tile + r * 128 + ((c ^ (r & 7)) << 4);
    asm volatile("ldmatrix.sync.aligned.m8n8.x2.shared.b16 {%0,%1}, [%2];"
                 : "=r"(bb[0]), "=r"(bb[1]) : "r"(addr));
}

__device__ __forceinline__ void mma_bf16(float* acc, const uint32_t* a, const uint32_t* bb) {
    asm volatile(
        "mma.sync.aligned.m16n8k16.row.col.f32.bf16.bf16.f32 "
        "{%0,%1,%2,%3}, {%4,%5,%6,%7}, {%8,%9}, {%0,%1,%2,%3};"
        : "+f"(acc[0]), "+f"(acc[1]), "+f"(acc[2]), "+f"(acc[3])
        : "r"(a[0]), "r"(a[1]), "r"(a[2]), "r"(a[3]), "r"(bb[0]), "r"(bb[1]));
}

// ---------------- zero scratch accumulators ----------------
__global__ void zero_kernel() {
    int i = blockIdx.x * blockDim.x + threadIdx.x;
    if (i < BATCH * NDIM) { d_Z[i] = 0.f; d_rowsum[i] = 0.f; }
}

// ---------------- W split prep: [Wq;Wk] fp32 -> bf16 hi/lo ----------------
__global__ __launch_bounds__(256) void wsplit_kernel(const float* __restrict__ Wq,
                                                     const float* __restrict__ Wk) {
    int idx = blockIdx.x * blockDim.x + threadIdx.x;
    if (idx >= 128 * CDIM) return;
    int m = idx >> 9;  // /512
    int c = idx & 511;
    float w = (m < 64) ? Wq[m * CDIM + c] : Wk[(m - 64) * CDIM + c];
    __nv_bfloat16 hi = __float2bfloat16(w);
    d_w_hi[idx] = hi;
    d_w_lo[idx] = __float2bfloat16(w - __bfloat162float(hi));
}

// ---------------- FG: [f;g] = [Wq;Wk] @ x[b] via bf16x3 mma.sync ----------------
// grid (32, BATCH), 256 threads (8 warps, 2x4).  Tile: [128 m] x [128 n=i], K=512
// in 8 chunks of 64.  Epilogue stages fp32 S[m][n] in smem, writes split bf16.
#define FG_SMEM (128 * 132 * 4)  // 67584 (operand region 65536 aliased below)

__global__ __launch_bounds__(256) void fg_kernel(const float* __restrict__ x) {
    extern __shared__ __align__(1024) char dynsm[];
    uint32_t smem_base = smem_u32(dynsm);
    uint4* sWhi = (uint4*)(dynsm);
    uint4* sWlo = (uint4*)(dynsm + 16384);
    uint4* sXhi = (uint4*)(dynsm + 32768);
    uint4* sXlo = (uint4*)(dynsm + 49152);
    float* S = (float*)dynsm;  // [128][132] (alias after mainloop)

    int b = blockIdx.y;
    int i0 = blockIdx.x * 128;
    int tid = threadIdx.x;
    int lane = tid & 31, wid = tid >> 5;
    int wm = wid >> 2, wn = wid & 3;
    const float* xb = x + (size_t)b * CDIM * NDIM;

    float acc[4][4][4];
    #pragma unroll
    for (int mf = 0; mf < 4; mf++)
        #pragma unroll
        for (int nf = 0; nf < 4; nf++)
            #pragma unroll
            for (int e = 0; e < 4; e++) acc[mf][nf][e] = 0.f;

    for (int c0 = 0; c0 < CDIM; c0 += 64) {
        // load W chunk [128 m][64 k] hi/lo (already bf16)
        #pragma unroll
        for (int t = 0; t < 4; t++) {
            int idx = tid + t * 256;           // 1024 uint4 tasks
            int m = idx >> 3, ch = idx & 7;
            int soff = m * 8 + (ch ^ (m & 7));
            sWhi[soff] = ((const uint4*)(d_w_hi + (size_t)m * CDIM + c0))[ch];
            sWlo[soff] = ((const uint4*)(d_w_lo + (size_t)m * CDIM + c0))[ch];
        }
        // load + convert x chunk -> transposed [128 n][64 k] bf16 hi/lo
        #pragma unroll
        for (int t = 0; t < 4; t++) {
            int idx = tid + t * 256;           // 1024 tasks: (n, k-octet)
            int n = idx & 127, oct = idx >> 7;
            const float* src = xb + (size_t)(c0 + oct * 8) * NDIM + i0 + n;
            __align__(16) __nv_bfloat16 h8[8], l8[8];
            #pragma unroll
            for (int j = 0; j < 8; j++) {
                float v = src[(size_t)j * NDIM];
                __nv_bfloat16 hi = __float2bfloat16(v);
                h8[j] = hi;
                l8[j] = __float2bfloat16(v - __bfloat162float(hi));
            }
            int soff = n * 8 + (oct ^ (n & 7));
            sXhi[soff] = *(uint4*)h8;
            sXlo[soff] = *(uint4*)l8;
        }
        __syncthreads();

        uint32_t tA = smem_base, tAlo = smem_base + 16384;
        uint32_t tB = smem_base + 32768, tBlo = smem_base + 49152;
        #pragma unroll
        for (int ks = 0; ks < 4; ks++) {
            int kc = ks * 2;
            uint32_t ahi[4][4], alo[4][4], bhi[4][2], blo[4][2];
            #pragma unroll
            for (int mf = 0; mf < 4; mf++) ldA(tA, wm * 64 + mf * 16, kc, lane, ahi[mf]);
            #pragma unroll
            for (int nf = 0; nf < 4; nf++) ldB(tB, wn * 32 + nf * 8, kc, lane, bhi[nf]);
            #pragma unroll
            for (int mf = 0; mf < 4; mf++)
                #pragma unroll
                for (int nf = 0; nf < 4; nf++) mma_bf16(acc[mf][nf], ahi[mf], bhi[nf]);
            #pragma unroll
            for (int mf = 0; mf < 4; mf++) ldA(tAlo, wm * 64 + mf * 16, kc, lane, alo[mf]);
            #pragma unroll
            for (int mf = 0; mf < 4; mf++)
                #pragma unroll
                for (int nf = 0; nf < 4; nf++) mma_bf16(acc[mf][nf], alo[mf], bhi[nf]);
            #pragma unroll
            for (int nf = 0; nf < 4; nf++) ldB(tBlo, wn * 32 + nf * 8, kc, lane, blo[nf]);
            #pragma unroll
            for (int mf = 0; mf < 4; mf++)
                #pragma unroll
                for (int nf = 0; nf < 4; nf++) mma_bf16(acc[mf][nf], ahi[mf], blo[nf]);
        }
        __syncthreads();
    }

    // stage fp32 S[m][n]
    #pragma unroll
    for (int mf = 0; mf < 4; mf++)
        #pragma unroll
        for (int nf = 0; nf < 4; nf++) {
            int r = wm * 64 + mf * 16 + (lane >> 2);
            int cc = wn * 32 + nf * 8 + (lane & 3) * 2;
            S[r * 132 + cc]           = acc[mf][nf][0];
            S[r * 132 + cc + 1]       = acc[mf][nf][1];
            S[(r + 8) * 132 + cc]     = acc[mf][nf][2];
            S[(r + 8) * 132 + cc + 1] = acc[mf][nf][3];
        }
    __syncthreads();

    // write split bf16 to [i][k] arrays: warp per i-row, lane -> (array, chunk)
    int arr = lane >> 3, chunk = lane & 7;
    int mbase = (arr >= 2 ? 64 : 0) + chunk * 8;
    __nv_bfloat16* dst = (arr == 0) ? d_fa_hi : (arr == 1) ? d_fa_lo
                       : (arr == 2) ? d_gb_hi : d_gb_lo;
    for (int r = wid; r < 128; r += 8) {
        __align__(16) __nv_bfloat16 vals[8];
        #pragma unroll
        for (int e = 0; e < 8; e++) {
            float v = S[(mbase + e) * 132 + r];
            __nv_bfloat16 hi = __float2bfloat16(v);
            if (arr & 1) vals[e] = __float2bfloat16(v - __bfloat162float(hi));
            else         vals[e] = hi;
        }
        *(uint4*)(dst + ((size_t)b * NDIM + i0 + r) * KDIM + chunk * 8) = *(uint4*)vals;
    }
}

// ---------------- attention passes: S = f^T g (split-bf16, 3 terms) ----------------
// grid (32,32,BATCH) = (jtile, itile, b), 256 threads (2x4 warp grid).
// Register-resident epilogue: no smem S staging.
// PASS 1: Z[b,j] += sum_i exp(s).  PASS 2: beta = exp(s)/Z, rowsum += sum_j beta.
#define ATTN_SMEM 66048  // operands 65536 + sZ 512

template <int PASS>
__global__ __launch_bounds__(256, 2) void attn_kernel(float* __restrict__ beta_out) {
    extern __shared__ __align__(1024) char dynsm[];
    uint32_t smem_base = smem_u32(dynsm);
    float* sZ = (float*)(dynsm + 65536);

    int b  = blockIdx.z;
    int i0 = blockIdx.y * 128;
    int j0 = blockIdx.x * 128;
    int tid = threadIdx.x;
    int lane = tid & 31, wid = tid >> 5;
    int wm = wid >> 2, wn = wid & 3;

    if (PASS == 2 && tid < 128)
        sZ[tid] = 1.0f / d_Z[b * NDIM + j0 + tid];

    {   // load 4 operand tiles with XOR-16B swizzle
        const uint4* gAhi = (const uint4*)(d_fa_hi + ((size_t)b * NDIM + i0) * KDIM);
        const uint4* gAlo = (const uint4*)(d_fa_lo + ((size_t)b * NDIM + i0) * KDIM);
        const uint4* gBhi = (const uint4*)(d_gb_hi + ((size_t)b * NDIM + j0) * KDIM);
        const uint4* gBlo = (const uint4*)(d_gb_lo + ((size_t)b * NDIM + j0) * KDIM);
        uint4* sAhi = (uint4*)(dynsm);
        uint4* sAlo = (uint4*)(dynsm + 16384);
        uint4* sBhi = (uint4*)(dynsm + 32768);
        uint4* sBlo = (uint4*)(dynsm + 49152);
        #pragma unroll
        for (int t = 0; t < 4; t++) {
            int idx = tid + t * 256;
            int r = idx >> 3, ch = idx & 7;
            int soff = r * 8 + (ch ^ (r & 7));
            sAhi[soff] = gAhi[idx];
            sAlo[soff] = gAlo[idx];
            sBhi[soff] = gBhi[idx];
            sBlo[soff] = gBlo[idx];
        }
    }
    __syncthreads();

    float acc[4][4][4];
    #pragma unroll
    for (int mf = 0; mf < 4; mf++)
        #pragma unroll
        for (int nf = 0; nf < 4; nf++)
            #pragma unroll
            for (int e = 0; e < 4; e++) acc[mf][nf][e] = 0.f;

    uint32_t tA = smem_base, tAlo = smem_base + 16384;
    uint32_t tB = smem_base + 32768, tBlo = smem_base + 49152;
    #pragma unroll
    for (int ks = 0; ks < 4; ks++) {
        int kc = ks * 2;
        uint32_t ahi[4][4], alo[4][4], bhi[4][2], blo[4][2];
        #pragma unroll
        for (int mf = 0; mf < 4; mf++) ldA(tA, wm * 64 + mf * 16, kc, lane, ahi[mf]);
        #pragma unroll
        for (int nf = 0; nf < 4; nf++) ldB(tB, wn * 32 + nf * 8, kc, lane, bhi[nf]);
        #pragma unroll
        for (int mf = 0; mf < 4; mf++)
            #pragma unroll
            for (int nf = 0; nf < 4; nf++) mma_bf16(acc[mf][nf], ahi[mf], bhi[nf]);
        #pragma unroll
        for (int mf = 0; mf < 4; mf++) ldA(tAlo, wm * 64 + mf * 16, kc, lane, alo[mf]);
        #pragma unroll
        for (int mf = 0; mf < 4; mf++)
            #pragma unroll
            for (int nf = 0; nf < 4; nf++) mma_bf16(acc[mf][nf], alo[mf], bhi[nf]);
        #pragma unroll
        for (int nf = 0; nf < 4; nf++) ldB(tBlo, wn * 32 + nf * 8, kc, lane, blo[nf]);
        #pragma unroll
        for (int mf = 0; mf < 4; mf++)
            #pragma unroll
            for (int nf = 0; nf < 4; nf++) mma_bf16(acc[mf][nf], ahi[mf], blo[nf]);
    }

    // -------- register-resident epilogue (no barriers needed) --------
    if (PASS == 1) {
        #pragma unroll
        for (int nf = 0; nf < 4; nf++) {
            float s0 = 0.f, s1 = 0.f;
            #pragma unroll
            for (int mf = 0; mf < 4; mf++) {
                s0 += fast_exp(acc[mf][nf][0]) + fast_exp(acc[mf][nf][2]);
                s1 += fast_exp(acc[mf][nf][1]) + fast_exp(acc[mf][nf][3]);
            }
            // reduce over the 8 row-groups (lanes sharing lane&3)
            #pragma unroll
            for (int o = 4; o < 32; o <<= 1) {
                s0 += __shfl_xor_sync(0xFFFFFFFFu, s0, o);
                s1 += __shfl_xor_sync(0xFFFFFFFFu, s1, o);
            }
            if (lane < 4) {
                int cc = wn * 32 + nf * 8 + lane * 2;
                atomicAdd(&d_Z[b * NDIM + j0 + cc], s0);
                atomicAdd(&d_Z[b * NDIM + j0 + cc + 1], s1);
            }
        }
    } else {
        float rs0[4], rs1[4];
        #pragma unroll
        for (int mf = 0; mf < 4; mf++) { rs0[mf] = 0.f; rs1[mf] = 0.f; }
        float* ob = beta_out + (size_t)b * NN;
        #pragma unroll
        for (int mf = 0; mf < 4; mf++) {
            int r = wm * 64 + mf * 16 + (lane >> 2);
            #pragma unroll
            for (int nf = 0; nf < 4; nf++) {
                int cc = wn * 32 + nf * 8 + (lane & 3) * 2;
                float iz0 = sZ[cc], iz1 = sZ[cc + 1];
                float v0 = fast_exp(acc[mf][nf][0]) * iz0;
                float v1 = fast_exp(acc[mf][nf][1]) * iz1;
                float v2 = fast_exp(acc[mf][nf][2]) * iz0;
                float v3 = fast_exp(acc[mf][nf][3]) * iz1;
                *(float2*)(ob + (size_t)(i0 + r) * NDIM + j0 + cc)     = make_float2(v0, v1);
                *(float2*)(ob + (size_t)(i0 + r + 8) * NDIM + j0 + cc) = make_float2(v2, v3);
                rs0[mf] += v0 + v1;
                rs1[mf] += v2 + v3;
            }
        }
        // reduce row sums over lanes sharing the same row (lane&3 varies)
        #pragma unroll
        for (int mf = 0; mf < 4; mf++) {
            #pragma unroll
            for (int o = 1; o < 4; o <<= 1) {
                rs0[mf] += __shfl_xor_sync(0xFFFFFFFFu, rs0[mf], o);
                rs1[mf] += __shfl_xor_sync(0xFFFFFFFFu, rs1[mf], o);
            }
        }
        if ((lane & 3) == 0) {
            #pragma unroll
            for (int mf = 0; mf < 4; mf++) {
                int r = wm * 64 + mf * 16 + (lane >> 2);
                atomicAdd(&d_rowsum[b * NDIM + i0 + r], rs0[mf]);
                atomicAdd(&d_rowsum[b * NDIM + i0 + r + 8], rs1[mf]);
            }
        }
    }
}

// ---------------- pooled epilogue ----------------
__global__ __launch_bounds__(256) void pool1_kernel(const float* __restrict__ x) {
    int b = blockIdx.y;
    int cc = blockIdx.x * 8 + (threadIdx.x >> 5);
    int lane = threadIdx.x & 31;
    const float* xr = x + ((size_t)b * CDIM + cc) * NDIM;
    const float* rs = d_rowsum + b * NDIM;
    float ay = 0.f, ax = 0.f;
    for (int i = lane; i < NDIM; i += 32) {
        float xv = xr[i];
        ay += xv * rs[i];
        ax += xv;
    }
    ay = warp_sum(ay); ax = warp_sum(ax);
    if (lane == 0) {
        d_y[b * CDIM + cc]    = ay * (1.0f / NDIM);
        d_xbar[b * CDIM + cc] = ax * (1.0f / NDIM);
    }
}

__global__ __launch_bounds__(256) void pool2_kernel(const float* __restrict__ Wv,
                                                    const float* __restrict__ gamma,
                                                    float* __restrict__ out) {
    int b = blockIdx.y;
    int c = blockIdx.x * 8 + (threadIdx.x >> 5);
    int lane = threadIdx.x & 31;
    const float* wr = Wv + (size_t)c * CDIM;
    const float* yb = d_y + b * CDIM;
    float a = 0.f;
    for (int k = lane; k < CDIM; k += 32) a += wr[k] * yb[k];
    a = warp_sum(a);
    if (lane == 0) out[b * CDIM + c] = gamma[0] * a + d_xbar[b * CDIM + c];
}

// ---------------- launch ----------------
extern "C" void kernel_launch(void* const* d_in, const int* in_sizes, int n_in,
                              void* d_out, int out_size) {
    const float* x     = (const float*)d_in[0];
    const float* Wq    = (const float*)d_in[1];
    const float* Wk    = (const float*)d_in[2];
    const float* Wv    = (const float*)d_in[3];
    const float* gamma = (const float*)d_in[4];
    float* out    = (float*)d_out;
    float* pooled = out;                 // [B,C,1,1] = 2048 floats
    float* beta   = out + BATCH * CDIM;  // [B,N,N]

    cudaFuncSetAttribute(fg_kernel, cudaFuncAttributeMaxDynamicSharedMemorySize, FG_SMEM);
    cudaFuncSetAttribute(attn_kernel<1>, cudaFuncAttributeMaxDynamicSharedMemorySize, ATTN_SMEM);
    cudaFuncSetAttribute(attn_kernel<2>, cudaFuncAttributeMaxDynamicSharedMemorySize, ATTN_SMEM);

    zero_kernel<<<64, 256>>>();
    wsplit_kernel<<<(128 * CDIM + 255) / 256, 256>>>(Wq, Wk);
    fg_kernel<<<dim3(32, BATCH), 256, FG_SMEM>>>(x);
    attn_kernel<1><<<dim3(32, 32, BATCH), 256, ATTN_SMEM>>>(beta);
    attn_kernel<2><<<dim3(32, 32, BATCH), 256, ATTN_SMEM>>>(beta);
    pool1_kernel<<<dim3(CDIM / 8, BATCH), 256>>>(x);
    pool2_kernel<<<dim3(CDIM / 8, BATCH), 256>>>(Wv, gamma, pooled);
}